// round 10
// baseline (speedup 1.0000x reference)
#include <cuda_runtime.h>
#include <cuda_fp16.h>
#include <math.h>
#include <cstdint>

// Problem constants
#define NB    16
#define NPTS  4096
#define MPTS  1024
#define CH2   256
#define CH1   128
#define OUT1  256
#define OUT2  256
#define LDA_W1 384

// ---- scratch ----
__device__ int    g_idx[NB * NPTS * 3];
__device__ float  g_wgt[NB * NPTS * 3];
__device__ __half g_Tth[NB * MPTS * OUT1];    // T transposed [b][m][o], HALF (gather src)
__device__ __half g_y1h[NB * OUT1 * NPTS];    // layer-1 activations, half
__device__ __half g_W1h[OUT1 * LDA_W1];
__device__ __half g_W2h[OUT2 * OUT1];
__device__ __half g_p1h[NB * CH1 * NPTS];
__device__ __half g_p2h[NB * CH2 * MPTS];

// ===========================================================================
__device__ __forceinline__ uint32_t smem_u32(const void* p) {
    uint32_t a;
    asm("{ .reg .u64 t; cvta.to.shared.u64 t, %1; cvt.u32.u64 %0, t; }" : "=r"(a) : "l"(p));
    return a;
}
__device__ __forceinline__ void cp16(void* dst, const void* src) {
    asm volatile("cp.async.ca.shared.global [%0], [%1], 16;"
                 :: "r"(smem_u32(dst)), "l"(src));
}
__device__ __forceinline__ void ldsm_x4(uint32_t addr, uint32_t& r0, uint32_t& r1,
                                        uint32_t& r2, uint32_t& r3) {
    asm volatile("ldmatrix.sync.aligned.m8n8.x4.shared.b16 {%0,%1,%2,%3}, [%4];"
                 : "=r"(r0), "=r"(r1), "=r"(r2), "=r"(r3) : "r"(addr));
}
__device__ __forceinline__ void ldsm_x4t(uint32_t addr, uint32_t& r0, uint32_t& r1,
                                         uint32_t& r2, uint32_t& r3) {
    asm volatile("ldmatrix.sync.aligned.m8n8.x4.trans.shared.b16 {%0,%1,%2,%3}, [%4];"
                 : "=r"(r0), "=r"(r1), "=r"(r2), "=r"(r3) : "r"(addr));
}

// ===========================================================================
// Kernel 0: convert weights + activations fp32 -> fp16 (rne)
// ===========================================================================
__global__ __launch_bounds__(256)
void conv_half_kernel(const float* __restrict__ W1, const float* __restrict__ W2,
                      const float* __restrict__ p1, const float* __restrict__ p2)
{
    const int idx0   = blockIdx.x * blockDim.x + threadIdx.x;
    const int stride = gridDim.x * blockDim.x;

    auto conv = [&](const float* __restrict__ src, __half* __restrict__ dst, int n4) {
        for (int i = idx0; i < n4; i += stride) {
            float4 v = reinterpret_cast<const float4*>(src)[i];
            __half2 h0 = __floats2half2_rn(v.x, v.y);
            __half2 h1 = __floats2half2_rn(v.z, v.w);
            reinterpret_cast<__half2*>(dst)[2 * i + 0] = h0;
            reinterpret_cast<__half2*>(dst)[2 * i + 1] = h1;
        }
    };
    conv(W1, g_W1h, OUT1 * LDA_W1 / 4);
    conv(W2, g_W2h, OUT2 * OUT1 / 4);
    conv(p1, g_p1h, NB * CH1 * NPTS / 4);
    conv(p2, g_p2h, NB * CH2 * MPTS / 4);
}

// ===========================================================================
// Kernel 1: three_nn + weights
// ===========================================================================
__global__ __launch_bounds__(256)
void three_nn_kernel(const float* __restrict__ xyz1, const float* __restrict__ xyz2)
{
    __shared__ float sx[MPTS], sy[MPTS], sz[MPTS], ss[MPTS];
    const int b = blockIdx.y;
    const float* x2 = xyz2 + (size_t)b * 3 * MPTS;
    for (int i = threadIdx.x; i < MPTS; i += blockDim.x) {
        float xv = x2[i], yv = x2[MPTS + i], zv = x2[2 * MPTS + i];
        sx[i] = xv; sy[i] = yv; sz[i] = zv;
        ss[i] = xv * xv + yv * yv + zv * zv;
    }
    __syncthreads();

    const int n = blockIdx.x * blockDim.x + threadIdx.x;
    const float* x1 = xyz1 + (size_t)b * 3 * NPTS;
    const float px = x1[n], py = x1[NPTS + n], pz = x1[2 * NPTS + n];
    const float sq1 = px * px + py * py + pz * pz;

    float d0 = 1e30f, d1 = 1e30f, d2 = 1e30f;
    int   i0 = 0, i1 = 0, i2 = 0;

    #pragma unroll 4
    for (int m = 0; m < MPTS; m++) {
        float inner = fmaf(px, sx[m], fmaf(py, sy[m], pz * sz[m]));
        float d = fmaf(-2.0f, inner, sq1 + ss[m]);
        if (d < d2) {
            if (d < d1) {
                d2 = d1; i2 = i1;
                if (d < d0) { d1 = d0; i1 = i0; d0 = d; i0 = m; }
                else        { d1 = d;  i1 = m; }
            } else { d2 = d; i2 = m; }
        }
    }

    float r0 = 1.0f / fmaxf(sqrtf(fmaxf(d0, 1e-20f)), 1e-10f);
    float r1 = 1.0f / fmaxf(sqrtf(fmaxf(d1, 1e-20f)), 1e-10f);
    float r2 = 1.0f / fmaxf(sqrtf(fmaxf(d2, 1e-20f)), 1e-10f);
    float inv = 1.0f / (r0 + r1 + r2);

    const int base = (b * NPTS + n) * 3;
    g_idx[base + 0] = i0; g_idx[base + 1] = i1; g_idx[base + 2] = i2;
    g_wgt[base + 0] = r0 * inv; g_wgt[base + 1] = r1 * inv; g_wgt[base + 2] = r2 * inv;
}

// ===========================================================================
// fp16 mma.sync (m16n8k16) GEMM with ldmatrix + cp.async double buffer.
// 256-thr CTA, 8 warps (2x4), CTA tile 128x128, warp tile 64x32, BK=32.
//   MODE 0: Tth = half((W1h[:, :256] @ p2h)^T)             -> g_Tth [m][o]
//   MODE 1: y1h = h(relu(W1h[:,256:]@p1h + b1 + gather))   -> g_y1h
//   MODE 2: out = relu(W2h @ y1h + b2)                     -> d_out f32
// MODE 1 gather: warp-cooperative coalesced loads of Tth rows, fp32 combine,
// staged via reused smem (stride 68, conflict-free), two 16-n passes.
// ===========================================================================
#define BK    32
#define ASTR  40     // halves per As row (32 + 8 pad)
#define BSTR  136    // halves per Bs row (128 + 8 pad)
#define AS_BYTES (2 * 128 * ASTR * 2)          // 20480
#define BS_BYTES (2 * BK * BSTR * 2)           // 17408
#define SMAIN_BYTES (AS_BYTES + BS_BYTES)      // 37888 (>= stage 34816)
#define STG_STRIDE 68                          // floats per staged row

template <int MODE>
__global__ __launch_bounds__(256, 2)
void gemm_mma(const float* __restrict__ bias, float* __restrict__ Cext)
{
    constexpr int K    = (MODE == 1) ? 128 : 256;
    constexpr int NC   = K / BK;
    constexpr int LDA  = (MODE == 2) ? 256 : LDA_W1;
    constexpr int COFF = (MODE == 1) ? 256 : 0;
    constexpr int LDX  = (MODE == 0) ? MPTS : NPTS;
    constexpr int XBS  = (MODE == 0) ? CH2 * MPTS : (MODE == 1) ? CH1 * NPTS : OUT1 * NPTS;

    const __half* Ah = (MODE == 2) ? g_W2h : g_W1h;
    const __half* Xh = (MODE == 0) ? g_p2h : (MODE == 1) ? g_p1h : g_y1h;

    __shared__ __align__(16) char s_main[SMAIN_BYTES];
    __half (*As)[128][ASTR] = reinterpret_cast<__half(*)[128][ASTR]>(s_main);
    __half (*Bs)[BK][BSTR]  = reinterpret_cast<__half(*)[BK][BSTR]>(s_main + AS_BYTES);
    float* s_stage = reinterpret_cast<float*>(s_main);   // reused post-mainloop
    __shared__ int   s_j[128 * 3];
    __shared__ float s_w[128 * 3];

    const int b     = blockIdx.z;
    const int nBase = blockIdx.x * 128;
    const int oBase = blockIdx.y * 128;
    const int tid   = threadIdx.x;
    const int wid   = tid >> 5;
    const int lane  = tid & 31;
    const int g     = lane >> 2;   // 0..7
    const int tc    = lane & 3;    // 0..3

    const int oW = (wid >> 2) * 64;   // 0 or 64
    const int nW = (wid & 3) * 32;    // 0,32,64,96

    const __half* Xb = Xh + (size_t)b * XBS;

    if (MODE == 1) {
        // preload idx/wgt metadata for this CTA's 128 n (synced by first barrier)
        const int*   gi = g_idx + ((size_t)b * NPTS + nBase) * 3;
        const float* gw = g_wgt + ((size_t)b * NPTS + nBase) * 3;
        for (int i = tid; i < 384; i += 256) { s_j[i] = gi[i]; s_w[i] = gw[i]; }
    }

    // cp.async task mapping
    const int arow = tid & 127;
    const int akc0 = tid >> 7;
    const int bk0  = tid >> 4;
    const int bn8  = tid & 15;

    auto prefetch = [&](int c) {
        const int buf = c & 1;
        const int k0  = c * BK;
        const __half* ap = &Ah[(size_t)(oBase + arow) * LDA + COFF + k0];
        cp16(&As[buf][arow][8 * akc0],       ap + 8 * akc0);
        cp16(&As[buf][arow][8 * (akc0 + 2)], ap + 8 * (akc0 + 2));
        const __half* bp = &Xb[(size_t)k0 * LDX + nBase + 8 * bn8];
        cp16(&Bs[buf][bk0     ][8 * bn8], bp + (size_t)bk0 * LDX);
        cp16(&Bs[buf][bk0 + 16][8 * bn8], bp + (size_t)(bk0 + 16) * LDX);
        asm volatile("cp.async.commit_group;" ::: "memory");
    };

    // ldmatrix per-lane address offsets (bytes)
    const int lm = lane >> 3;
    const int lr = lane & 7;
    uint32_t aoff[4];
    #pragma unroll
    for (int mi = 0; mi < 4; mi++)
        aoff[mi] = ((oW + mi * 16 + lr + 8 * (lm & 1)) * ASTR + 8 * (lm >> 1)) * 2;
    uint32_t boff[2];
    #pragma unroll
    for (int pr = 0; pr < 2; pr++)
        boff[pr] = ((lr + 8 * (lm & 1)) * BSTR + nW + pr * 16 + 8 * (lm >> 1)) * 2;

    const uint32_t as_base = smem_u32(&As[0][0][0]);
    const uint32_t bs_base = smem_u32(&Bs[0][0][0]);
    constexpr uint32_t AS_BUF = 128 * ASTR * 2;
    constexpr uint32_t BS_BUF = BK * BSTR * 2;

    float c[4][4][4];
    #pragma unroll
    for (int mi = 0; mi < 4; mi++)
        #pragma unroll
        for (int ni = 0; ni < 4; ni++)
            #pragma unroll
            for (int q = 0; q < 4; q++) c[mi][ni][q] = 0.0f;

    prefetch(0);
    asm volatile("cp.async.wait_group 0;" ::: "memory");
    __syncthreads();

    for (int cc = 0; cc < NC; cc++) {
        const uint32_t asb = as_base + (cc & 1) * AS_BUF;
        const uint32_t bsb = bs_base + (cc & 1) * BS_BUF;
        if (cc + 1 < NC) prefetch(cc + 1);

        #pragma unroll
        for (int kk = 0; kk < BK; kk += 16) {
            uint32_t a[4][4];
            #pragma unroll
            for (int mi = 0; mi < 4; mi++)
                ldsm_x4(asb + aoff[mi] + kk * 2, a[mi][0], a[mi][1], a[mi][2], a[mi][3]);
            uint32_t bb[4][2];
            ldsm_x4t(bsb + boff[0] + kk * (BSTR * 2), bb[0][0], bb[0][1], bb[1][0], bb[1][1]);
            ldsm_x4t(bsb + boff[1] + kk * (BSTR * 2), bb[2][0], bb[2][1], bb[3][0], bb[3][1]);
            #pragma unroll
            for (int mi = 0; mi < 4; mi++)
                #pragma unroll
                for (int ni = 0; ni < 4; ni++) {
                    asm volatile(
                        "mma.sync.aligned.m16n8k16.row.col.f32.f16.f16.f32 "
                        "{%0,%1,%2,%3}, {%4,%5,%6,%7}, {%8,%9}, {%0,%1,%2,%3};"
                        : "+f"(c[mi][ni][0]), "+f"(c[mi][ni][1]),
                          "+f"(c[mi][ni][2]), "+f"(c[mi][ni][3])
                        : "r"(a[mi][0]), "r"(a[mi][1]), "r"(a[mi][2]), "r"(a[mi][3]),
                          "r"(bb[ni][0]), "r"(bb[ni][1]));
                }
        }

        asm volatile("cp.async.wait_group 0;" ::: "memory");
        __syncthreads();
    }

    // ---- epilogue ----
    // element (mi, ni, q): o = oBase+oW+mi*16+g+(q>=2)*8 ; n = nBase+nW+ni*8+tc*2+(q&1)

    if (MODE == 0) {
        __half* Cb = g_Tth + (size_t)b * MPTS * OUT1;
        #pragma unroll
        for (int ni = 0; ni < 4; ni++) {
            #pragma unroll
            for (int t = 0; t < 2; t++) {
                int m = nBase + nW + ni * 8 + tc * 2 + t;
                __half* mrow = Cb + (size_t)m * OUT1;
                #pragma unroll
                for (int mi = 0; mi < 4; mi++) {
                    #pragma unroll
                    for (int h = 0; h < 2; h++) {
                        int o = oBase + oW + mi * 16 + g + h * 8;
                        mrow[o] = __float2half_rn(c[mi][ni][h * 2 + t]);
                    }
                }
            }
        }
        return;
    }

    if (MODE == 1) {
        // --- warp-cooperative staged gather ---
        const __half* Tb = g_Tth + (size_t)b * MPTS * OUT1;
        float* stg = s_stage + wid * (16 * STG_STRIDE);
        const int ocol = oBase + oW + 2 * lane;   // this lane's 2 o-values

        #pragma unroll
        for (int p = 0; p < 2; p++) {
            // phase A: stage 16 n rows (coalesced __half2 loads, fp32 combine)
            #pragma unroll 4
            for (int s = 0; s < 16; s++) {
                const int ncta = nW + p * 16 + s;
                const int j0 = s_j[ncta * 3 + 0];
                const int j1 = s_j[ncta * 3 + 1];
                const int j2 = s_j[ncta * 3 + 2];
                const float w0 = s_w[ncta * 3 + 0];
                const float w1 = s_w[ncta * 3 + 1];
                const float w2 = s_w[ncta * 3 + 2];
                float2 f0 = __half22float2(
                    *reinterpret_cast<const __half2*>(Tb + (size_t)j0 * OUT1 + ocol));
                float2 f1 = __half22float2(
                    *reinterpret_cast<const __half2*>(Tb + (size_t)j1 * OUT1 + ocol));
                float2 f2 = __half22float2(
                    *reinterpret_cast<const __half2*>(Tb + (size_t)j2 * OUT1 + ocol));
                float2 r;
                r.x = w0 * f0.x + w1 * f1.x + w2 * f2.x;
                r.y = w0 * f0.y + w1 * f1.y + w2 * f2.y;
                *reinterpret_cast<float2*>(stg + s * STG_STRIDE + 2 * lane) = r;
            }
            __syncwarp();
            // phase B: consume ni in {2p, 2p+1}
            #pragma unroll
            for (int nn = 0; nn < 2; nn++) {
                const int ni = 2 * p + nn;
                #pragma unroll
                for (int t = 0; t < 2; t++) {
                    const int s = nn * 8 + tc * 2 + t;
                    #pragma unroll
                    for (int mi = 0; mi < 4; mi++)
                        #pragma unroll
                        for (int h = 0; h < 2; h++) {
                            const int ol = mi * 16 + 8 * h + g;
                            c[mi][ni][h * 2 + t] += stg[s * STG_STRIDE + ol];
                        }
                }
            }
            __syncwarp();
        }

        // bias + relu + half store
        __half* Cb = g_y1h + (size_t)b * OUT1 * NPTS;
        #pragma unroll
        for (int mi = 0; mi < 4; mi++) {
            #pragma unroll
            for (int h = 0; h < 2; h++) {
                int o = oBase + oW + mi * 16 + g + h * 8;
                float bv = bias[o];
                __half* orow = Cb + (size_t)o * NPTS;
                #pragma unroll
                for (int ni = 0; ni < 4; ni++) {
                    int n = nBase + nW + ni * 8 + tc * 2;
                    float v0 = fmaxf(c[mi][ni][h * 2 + 0] + bv, 0.0f);
                    float v1 = fmaxf(c[mi][ni][h * 2 + 1] + bv, 0.0f);
                    *reinterpret_cast<__half2*>(&orow[n]) = __floats2half2_rn(v0, v1);
                }
            }
        }
        return;
    }

    // MODE 2: final output fp32
    float* Cb = Cext + (size_t)b * OUT2 * NPTS;
    #pragma unroll
    for (int mi = 0; mi < 4; mi++) {
        #pragma unroll
        for (int h = 0; h < 2; h++) {
            int o = oBase + oW + mi * 16 + g + h * 8;
            float bv = bias[o];
            float* orow = Cb + (size_t)o * NPTS;
            #pragma unroll
            for (int ni = 0; ni < 4; ni++) {
                int n = nBase + nW + ni * 8 + tc * 2;
                float v0 = fmaxf(c[mi][ni][h * 2 + 0] + bv, 0.0f);
                float v1 = fmaxf(c[mi][ni][h * 2 + 1] + bv, 0.0f);
                *reinterpret_cast<float2*>(&orow[n]) = make_float2(v0, v1);
            }
        }
    }
}

// ===========================================================================
extern "C" void kernel_launch(void* const* d_in, const int* in_sizes, int n_in,
                              void* d_out, int out_size)
{
    const float* xyz1    = (const float*)d_in[0];
    const float* xyz2    = (const float*)d_in[1];
    const float* points1 = (const float*)d_in[2];
    const float* points2 = (const float*)d_in[3];
    const float* W1      = (const float*)d_in[4];
    const float* b1      = (const float*)d_in[5];
    const float* W2      = (const float*)d_in[6];
    const float* b2      = (const float*)d_in[7];
    float*       out     = (float*)d_out;

    conv_half_kernel<<<1024, 256>>>(W1, W2, points1, points2);

    three_nn_kernel<<<dim3(NPTS / 256, NB), 256>>>(xyz1, xyz2);

    // Tth = half((W1[:, :256] @ points2)^T)
    gemm_mma<0><<<dim3(MPTS / 128, OUT1 / 128, NB), 256>>>(nullptr, nullptr);

    // y1h = half(relu(W1[:, 256:] @ points1 + b1 + gathered Tth))
    gemm_mma<1><<<dim3(NPTS / 128, OUT1 / 128, NB), 256>>>(b1, nullptr);

    // out = relu(W2 @ y1h + b2)
    gemm_mma<2><<<dim3(NPTS / 128, OUT2 / 128, NB), 256>>>(b2, out);
}

// round 11
// speedup vs baseline: 1.0412x; 1.0412x over previous
#include <cuda_runtime.h>
#include <cuda_fp16.h>
#include <math.h>
#include <cstdint>

// Problem constants
#define NB    16
#define NPTS  4096
#define MPTS  1024
#define CH2   256
#define CH1   128
#define OUT1  256
#define OUT2  256
#define LDA_W1 384

// ---- scratch ----
__device__ int    g_idx[NB * NPTS * 3];
__device__ float  g_wgt[NB * NPTS * 3];
__device__ float  g_Tt [NB * MPTS * OUT1];    // T transposed [b][m][o], fp32 (gather src)
__device__ __half g_y1h[NB * OUT1 * NPTS];    // layer-1 activations, half
__device__ __half g_W1h[OUT1 * LDA_W1];
__device__ __half g_W2h[OUT2 * OUT1];
__device__ __half g_p1h[NB * CH1 * NPTS];
__device__ __half g_p2h[NB * CH2 * MPTS];

// ===========================================================================
__device__ __forceinline__ uint32_t smem_u32(const void* p) {
    uint32_t a;
    asm("{ .reg .u64 t; cvta.to.shared.u64 t, %1; cvt.u32.u64 %0, t; }" : "=r"(a) : "l"(p));
    return a;
}
__device__ __forceinline__ void cp16(void* dst, const void* src) {
    asm volatile("cp.async.ca.shared.global [%0], [%1], 16;"
                 :: "r"(smem_u32(dst)), "l"(src));
}
__device__ __forceinline__ void ldsm_x4(uint32_t addr, uint32_t& r0, uint32_t& r1,
                                        uint32_t& r2, uint32_t& r3) {
    asm volatile("ldmatrix.sync.aligned.m8n8.x4.shared.b16 {%0,%1,%2,%3}, [%4];"
                 : "=r"(r0), "=r"(r1), "=r"(r2), "=r"(r3) : "r"(addr));
}
__device__ __forceinline__ void ldsm_x4t(uint32_t addr, uint32_t& r0, uint32_t& r1,
                                         uint32_t& r2, uint32_t& r3) {
    asm volatile("ldmatrix.sync.aligned.m8n8.x4.trans.shared.b16 {%0,%1,%2,%3}, [%4];"
                 : "=r"(r0), "=r"(r1), "=r"(r2), "=r"(r3) : "r"(addr));
}

// ===========================================================================
// Kernel 0: convert weights + activations fp32 -> fp16 (rne)
// ===========================================================================
__global__ __launch_bounds__(256)
void conv_half_kernel(const float* __restrict__ W1, const float* __restrict__ W2,
                      const float* __restrict__ p1, const float* __restrict__ p2)
{
    const int idx0   = blockIdx.x * blockDim.x + threadIdx.x;
    const int stride = gridDim.x * blockDim.x;

    auto conv = [&](const float* __restrict__ src, __half* __restrict__ dst, int n4) {
        for (int i = idx0; i < n4; i += stride) {
            float4 v = reinterpret_cast<const float4*>(src)[i];
            __half2 h0 = __floats2half2_rn(v.x, v.y);
            __half2 h1 = __floats2half2_rn(v.z, v.w);
            reinterpret_cast<__half2*>(dst)[2 * i + 0] = h0;
            reinterpret_cast<__half2*>(dst)[2 * i + 1] = h1;
        }
    };
    conv(W1, g_W1h, OUT1 * LDA_W1 / 4);
    conv(W2, g_W2h, OUT2 * OUT1 / 4);
    conv(p1, g_p1h, NB * CH1 * NPTS / 4);
    conv(p2, g_p2h, NB * CH2 * MPTS / 4);
}

// ===========================================================================
// Kernel 1: three_nn + weights
// ===========================================================================
__global__ __launch_bounds__(256)
void three_nn_kernel(const float* __restrict__ xyz1, const float* __restrict__ xyz2)
{
    __shared__ float sx[MPTS], sy[MPTS], sz[MPTS], ss[MPTS];
    const int b = blockIdx.y;
    const float* x2 = xyz2 + (size_t)b * 3 * MPTS;
    for (int i = threadIdx.x; i < MPTS; i += blockDim.x) {
        float xv = x2[i], yv = x2[MPTS + i], zv = x2[2 * MPTS + i];
        sx[i] = xv; sy[i] = yv; sz[i] = zv;
        ss[i] = xv * xv + yv * yv + zv * zv;
    }
    __syncthreads();

    const int n = blockIdx.x * blockDim.x + threadIdx.x;
    const float* x1 = xyz1 + (size_t)b * 3 * NPTS;
    const float px = x1[n], py = x1[NPTS + n], pz = x1[2 * NPTS + n];
    const float sq1 = px * px + py * py + pz * pz;

    float d0 = 1e30f, d1 = 1e30f, d2 = 1e30f;
    int   i0 = 0, i1 = 0, i2 = 0;

    #pragma unroll 4
    for (int m = 0; m < MPTS; m++) {
        float inner = fmaf(px, sx[m], fmaf(py, sy[m], pz * sz[m]));
        float d = fmaf(-2.0f, inner, sq1 + ss[m]);
        if (d < d2) {
            if (d < d1) {
                d2 = d1; i2 = i1;
                if (d < d0) { d1 = d0; i1 = i0; d0 = d; i0 = m; }
                else        { d1 = d;  i1 = m; }
            } else { d2 = d; i2 = m; }
        }
    }

    float r0 = 1.0f / fmaxf(sqrtf(fmaxf(d0, 1e-20f)), 1e-10f);
    float r1 = 1.0f / fmaxf(sqrtf(fmaxf(d1, 1e-20f)), 1e-10f);
    float r2 = 1.0f / fmaxf(sqrtf(fmaxf(d2, 1e-20f)), 1e-10f);
    float inv = 1.0f / (r0 + r1 + r2);

    const int base = (b * NPTS + n) * 3;
    g_idx[base + 0] = i0; g_idx[base + 1] = i1; g_idx[base + 2] = i2;
    g_wgt[base + 0] = r0 * inv; g_wgt[base + 1] = r1 * inv; g_wgt[base + 2] = r2 * inv;
}

// ===========================================================================
// fp16 mma.sync (m16n8k16) GEMM with ldmatrix + cp.async double buffer.
// 256-thr CTA, 8 warps (2x4), CTA tile 128x128, warp tile 64x32, BK=32.
//   MODE 0: Tt  = (W1h[:, :256] @ p2h)^T                  -> g_Tt [m][o] f32
//   MODE 1: y1h = h(relu(W1h[:,256:]@p1h + b1 + gather))  -> g_y1h
//   MODE 2: out = relu(W2h @ y1h + b2)                    -> d_out f32
// MODE 1: scattered gather is INTERLEAVED into the chunk loop (ni group
// (cc+3)&3 gathered in chunk cc), overlapping LDG latency/L1 work with mma.
// ===========================================================================
#define BK    32
#define ASTR  40     // halves per As row (32 + 8 pad)
#define BSTR  136    // halves per Bs row (128 + 8 pad)

template <int MODE>
__global__ __launch_bounds__(256, 2)
void gemm_mma(const float* __restrict__ bias, float* __restrict__ Cext)
{
    constexpr int K    = (MODE == 1) ? 128 : 256;
    constexpr int NC   = K / BK;
    constexpr int LDA  = (MODE == 2) ? 256 : LDA_W1;
    constexpr int COFF = (MODE == 1) ? 256 : 0;
    constexpr int LDX  = (MODE == 0) ? MPTS : NPTS;
    constexpr int XBS  = (MODE == 0) ? CH2 * MPTS : (MODE == 1) ? CH1 * NPTS : OUT1 * NPTS;

    const __half* Ah = (MODE == 2) ? g_W2h : g_W1h;
    const __half* Xh = (MODE == 0) ? g_p2h : (MODE == 1) ? g_p1h : g_y1h;

    __shared__ __align__(16) __half As[2][128][ASTR];   // 20.0 KB
    __shared__ __align__(16) __half Bs[2][BK][BSTR];    // 17.4 KB
    __shared__ int   s_j[128 * 3];
    __shared__ float s_w[128 * 3];

    const int b     = blockIdx.z;
    const int nBase = blockIdx.x * 128;
    const int oBase = blockIdx.y * 128;
    const int tid   = threadIdx.x;
    const int wid   = tid >> 5;
    const int lane  = tid & 31;
    const int g     = lane >> 2;   // 0..7
    const int tc    = lane & 3;    // 0..3

    const int oW = (wid >> 2) * 64;   // 0 or 64
    const int nW = (wid & 3) * 32;    // 0,32,64,96

    const __half* Xb = Xh + (size_t)b * XBS;

    if (MODE == 1) {
        // preload idx/wgt metadata (visibility covered by first __syncthreads)
        const int*   gi = g_idx + ((size_t)b * NPTS + nBase) * 3;
        const float* gw = g_wgt + ((size_t)b * NPTS + nBase) * 3;
        for (int i = tid; i < 384; i += 256) { s_j[i] = gi[i]; s_w[i] = gw[i]; }
    }

    // cp.async task mapping
    const int arow = tid & 127;
    const int akc0 = tid >> 7;
    const int bk0  = tid >> 4;
    const int bn8  = tid & 15;

    auto prefetch = [&](int c) {
        const int buf = c & 1;
        const int k0  = c * BK;
        const __half* ap = &Ah[(size_t)(oBase + arow) * LDA + COFF + k0];
        cp16(&As[buf][arow][8 * akc0],       ap + 8 * akc0);
        cp16(&As[buf][arow][8 * (akc0 + 2)], ap + 8 * (akc0 + 2));
        const __half* bp = &Xb[(size_t)k0 * LDX + nBase + 8 * bn8];
        cp16(&Bs[buf][bk0     ][8 * bn8], bp + (size_t)bk0 * LDX);
        cp16(&Bs[buf][bk0 + 16][8 * bn8], bp + (size_t)(bk0 + 16) * LDX);
        asm volatile("cp.async.commit_group;" ::: "memory");
    };

    // ldmatrix per-lane address offsets (bytes)
    const int lm = lane >> 3;
    const int lr = lane & 7;
    uint32_t aoff[4];
    #pragma unroll
    for (int mi = 0; mi < 4; mi++)
        aoff[mi] = ((oW + mi * 16 + lr + 8 * (lm & 1)) * ASTR + 8 * (lm >> 1)) * 2;
    uint32_t boff[2];
    #pragma unroll
    for (int pr = 0; pr < 2; pr++)
        boff[pr] = ((lr + 8 * (lm & 1)) * BSTR + nW + pr * 16 + 8 * (lm >> 1)) * 2;

    const uint32_t as_base = smem_u32(&As[0][0][0]);
    const uint32_t bs_base = smem_u32(&Bs[0][0][0]);
    constexpr uint32_t AS_BUF = 128 * ASTR * 2;
    constexpr uint32_t BS_BUF = BK * BSTR * 2;

    const float* Tb = g_Tt + (size_t)b * MPTS * OUT1;

    float c[4][4][4];
    #pragma unroll
    for (int mi = 0; mi < 4; mi++)
        #pragma unroll
        for (int ni = 0; ni < 4; ni++)
            #pragma unroll
            for (int q = 0; q < 4; q++) c[mi][ni][q] = 0.0f;

    prefetch(0);
    asm volatile("cp.async.wait_group 0;" ::: "memory");
    __syncthreads();

    for (int cc = 0; cc < NC; cc++) {
        const uint32_t asb = as_base + (cc & 1) * AS_BUF;
        const uint32_t bsb = bs_base + (cc & 1) * BS_BUF;
        if (cc + 1 < NC) prefetch(cc + 1);

        #pragma unroll
        for (int kk = 0; kk < BK; kk += 16) {
            uint32_t a[4][4];
            #pragma unroll
            for (int mi = 0; mi < 4; mi++)
                ldsm_x4(asb + aoff[mi] + kk * 2, a[mi][0], a[mi][1], a[mi][2], a[mi][3]);
            uint32_t bb[4][2];
            ldsm_x4t(bsb + boff[0] + kk * (BSTR * 2), bb[0][0], bb[0][1], bb[1][0], bb[1][1]);
            ldsm_x4t(bsb + boff[1] + kk * (BSTR * 2), bb[2][0], bb[2][1], bb[3][0], bb[3][1]);
            #pragma unroll
            for (int mi = 0; mi < 4; mi++)
                #pragma unroll
                for (int ni = 0; ni < 4; ni++) {
                    asm volatile(
                        "mma.sync.aligned.m16n8k16.row.col.f32.f16.f16.f32 "
                        "{%0,%1,%2,%3}, {%4,%5,%6,%7}, {%8,%9}, {%0,%1,%2,%3};"
                        : "+f"(c[mi][ni][0]), "+f"(c[mi][ni][1]),
                          "+f"(c[mi][ni][2]), "+f"(c[mi][ni][3])
                        : "r"(a[mi][0]), "r"(a[mi][1]), "r"(a[mi][2]), "r"(a[mi][3]),
                          "r"(bb[ni][0]), "r"(bb[ni][1]));
                }
        }

        if (MODE == 1) {
            // interleaved scattered gather for ni group (cc+3)%4:
            // max register-dependency distance to next chunk's mma on same c regs
            const int gni = (cc + 3) & 3;
            #pragma unroll
            for (int t = 0; t < 2; t++) {
                const int ncta = nW + gni * 8 + tc * 2 + t;
                const int j0 = s_j[ncta * 3 + 0];
                const int j1 = s_j[ncta * 3 + 1];
                const int j2 = s_j[ncta * 3 + 2];
                const float w0 = s_w[ncta * 3 + 0];
                const float w1 = s_w[ncta * 3 + 1];
                const float w2 = s_w[ncta * 3 + 2];
                const float* r0 = Tb + (size_t)j0 * OUT1 + oBase + oW;
                const float* r1 = Tb + (size_t)j1 * OUT1 + oBase + oW;
                const float* r2 = Tb + (size_t)j2 * OUT1 + oBase + oW;
                #pragma unroll
                for (int mi = 0; mi < 4; mi++) {
                    #pragma unroll
                    for (int h = 0; h < 2; h++) {
                        const int ol = mi * 16 + g + h * 8;
                        c[mi][gni][h * 2 + t] +=
                            w0 * __ldg(&r0[ol]) + w1 * __ldg(&r1[ol]) + w2 * __ldg(&r2[ol]);
                    }
                }
            }
        }

        asm volatile("cp.async.wait_group 0;" ::: "memory");
        __syncthreads();
    }

    // ---- epilogue ----
    // element (mi, ni, q): o = oBase+oW+mi*16+g+(q>=2)*8 ; n = nBase+nW+ni*8+tc*2+(q&1)

    if (MODE == 0) {
        float* Cb = g_Tt + (size_t)b * MPTS * OUT1;
        #pragma unroll
        for (int ni = 0; ni < 4; ni++) {
            #pragma unroll
            for (int t = 0; t < 2; t++) {
                int m = nBase + nW + ni * 8 + tc * 2 + t;
                float* mrow = Cb + (size_t)m * OUT1;
                #pragma unroll
                for (int mi = 0; mi < 4; mi++) {
                    #pragma unroll
                    for (int h = 0; h < 2; h++) {
                        int o = oBase + oW + mi * 16 + g + h * 8;
                        mrow[o] = c[mi][ni][h * 2 + t];
                    }
                }
            }
        }
        return;
    }

    if (MODE == 1) {
        // bias + relu + half store
        __half* Cb = g_y1h + (size_t)b * OUT1 * NPTS;
        #pragma unroll
        for (int mi = 0; mi < 4; mi++) {
            #pragma unroll
            for (int h = 0; h < 2; h++) {
                int o = oBase + oW + mi * 16 + g + h * 8;
                float bv = bias[o];
                __half* orow = Cb + (size_t)o * NPTS;
                #pragma unroll
                for (int ni = 0; ni < 4; ni++) {
                    int n = nBase + nW + ni * 8 + tc * 2;
                    float v0 = fmaxf(c[mi][ni][h * 2 + 0] + bv, 0.0f);
                    float v1 = fmaxf(c[mi][ni][h * 2 + 1] + bv, 0.0f);
                    *reinterpret_cast<__half2*>(&orow[n]) = __floats2half2_rn(v0, v1);
                }
            }
        }
        return;
    }

    // MODE 2: final output fp32
    float* Cb = Cext + (size_t)b * OUT2 * NPTS;
    #pragma unroll
    for (int mi = 0; mi < 4; mi++) {
        #pragma unroll
        for (int h = 0; h < 2; h++) {
            int o = oBase + oW + mi * 16 + g + h * 8;
            float bv = bias[o];
            float* orow = Cb + (size_t)o * NPTS;
            #pragma unroll
            for (int ni = 0; ni < 4; ni++) {
                int n = nBase + nW + ni * 8 + tc * 2;
                float v0 = fmaxf(c[mi][ni][h * 2 + 0] + bv, 0.0f);
                float v1 = fmaxf(c[mi][ni][h * 2 + 1] + bv, 0.0f);
                *reinterpret_cast<float2*>(&orow[n]) = make_float2(v0, v1);
            }
        }
    }
}

// ===========================================================================
extern "C" void kernel_launch(void* const* d_in, const int* in_sizes, int n_in,
                              void* d_out, int out_size)
{
    const float* xyz1    = (const float*)d_in[0];
    const float* xyz2    = (const float*)d_in[1];
    const float* points1 = (const float*)d_in[2];
    const float* points2 = (const float*)d_in[3];
    const float* W1      = (const float*)d_in[4];
    const float* b1      = (const float*)d_in[5];
    const float* W2      = (const float*)d_in[6];
    const float* b2      = (const float*)d_in[7];
    float*       out     = (float*)d_out;

    conv_half_kernel<<<1024, 256>>>(W1, W2, points1, points2);

    three_nn_kernel<<<dim3(NPTS / 256, NB), 256>>>(xyz1, xyz2);

    // Tt = (W1[:, :256] @ points2)^T   (fp32)
    gemm_mma<0><<<dim3(MPTS / 128, OUT1 / 128, NB), 256>>>(nullptr, nullptr);

    // y1h = half(relu(W1[:, 256:] @ points1 + b1 + gathered Tt))
    gemm_mma<1><<<dim3(NPTS / 128, OUT1 / 128, NB), 256>>>(b1, nullptr);

    // out = relu(W2 @ y1h + b2)
    gemm_mma<2><<<dim3(NPTS / 128, OUT2 / 128, NB), 256>>>(b2, out);
}

// round 12
// speedup vs baseline: 1.1047x; 1.0610x over previous
#include <cuda_runtime.h>
#include <cuda_fp16.h>
#include <math.h>
#include <cstdint>

// Problem constants
#define NB    16
#define NPTS  4096
#define MPTS  1024
#define CH2   256
#define CH1   128
#define OUT1  256
#define OUT2  256
#define LDA_W1 384

// ---- scratch ----
__device__ int    g_idx[NB * NPTS * 3];
__device__ float  g_wgt[NB * NPTS * 3];
__device__ float  g_Tt [NB * MPTS * OUT1];    // T transposed [b][m][o], fp32 (gather src)
__device__ __half g_y1h[NB * OUT1 * NPTS];    // layer-1 activations, half
__device__ __half g_W1h[OUT1 * LDA_W1];
__device__ __half g_W2h[OUT2 * OUT1];
__device__ __half g_p1h[NB * CH1 * NPTS];
__device__ __half g_p2h[NB * CH2 * MPTS];

// ===========================================================================
__device__ __forceinline__ uint32_t smem_u32(const void* p) {
    uint32_t a;
    asm("{ .reg .u64 t; cvta.to.shared.u64 t, %1; cvt.u32.u64 %0, t; }" : "=r"(a) : "l"(p));
    return a;
}
__device__ __forceinline__ void cp16(void* dst, const void* src) {
    asm volatile("cp.async.ca.shared.global [%0], [%1], 16;"
                 :: "r"(smem_u32(dst)), "l"(src));
}
__device__ __forceinline__ void ldsm_x4(uint32_t addr, uint32_t& r0, uint32_t& r1,
                                        uint32_t& r2, uint32_t& r3) {
    asm volatile("ldmatrix.sync.aligned.m8n8.x4.shared.b16 {%0,%1,%2,%3}, [%4];"
                 : "=r"(r0), "=r"(r1), "=r"(r2), "=r"(r3) : "r"(addr));
}
__device__ __forceinline__ void ldsm_x4t(uint32_t addr, uint32_t& r0, uint32_t& r1,
                                         uint32_t& r2, uint32_t& r3) {
    asm volatile("ldmatrix.sync.aligned.m8n8.x4.trans.shared.b16 {%0,%1,%2,%3}, [%4];"
                 : "=r"(r0), "=r"(r1), "=r"(r2), "=r"(r3) : "r"(addr));
}

// ===========================================================================
// Kernel A (merged): blocks [0,256) = three_nn ; blocks [256,512) = fp32->fp16
// conversion of W1/W2/points1/points2. The two halves are independent and
// overlap on the chip instead of running serially as two launches.
// ===========================================================================
__global__ __launch_bounds__(256)
void prep_kernel(const float* __restrict__ xyz1, const float* __restrict__ xyz2,
                 const float* __restrict__ W1,  const float* __restrict__ W2,
                 const float* __restrict__ p1,  const float* __restrict__ p2)
{
    __shared__ float4 s_p2[MPTS];   // (x, y, z, |p|^2)

    const int blk = blockIdx.x;
    const int tid = threadIdx.x;

    if (blk >= 256) {
        // ---- conversion half ----
        const int idx0   = (blk - 256) * 256 + tid;
        const int stride = 256 * 256;
        auto conv = [&](const float* __restrict__ src, __half* __restrict__ dst, int n4) {
            for (int i = idx0; i < n4; i += stride) {
                float4 v = reinterpret_cast<const float4*>(src)[i];
                reinterpret_cast<__half2*>(dst)[2 * i + 0] = __floats2half2_rn(v.x, v.y);
                reinterpret_cast<__half2*>(dst)[2 * i + 1] = __floats2half2_rn(v.z, v.w);
            }
        };
        conv(W1, g_W1h, OUT1 * LDA_W1 / 4);
        conv(W2, g_W2h, OUT2 * OUT1 / 4);
        conv(p1, g_p1h, NB * CH1 * NPTS / 4);
        conv(p2, g_p2h, NB * CH2 * MPTS / 4);
        return;
    }

    // ---- three_nn half ----
    const int b    = blk >> 4;          // 0..15
    const int nblk = blk & 15;          // 0..15
    const float* x2 = xyz2 + (size_t)b * 3 * MPTS;
    for (int i = tid; i < MPTS; i += 256) {
        float xv = x2[i], yv = x2[MPTS + i], zv = x2[2 * MPTS + i];
        s_p2[i] = make_float4(xv, yv, zv, xv * xv + yv * yv + zv * zv);
    }
    __syncthreads();

    const int n = nblk * 256 + tid;
    const float* x1 = xyz1 + (size_t)b * 3 * NPTS;
    const float px = x1[n], py = x1[NPTS + n], pz = x1[2 * NPTS + n];
    const float sq1 = px * px + py * py + pz * pz;

    float d0 = 1e30f, d1 = 1e30f, d2 = 1e30f;
    int   i0 = 0, i1 = 0, i2 = 0;

    #pragma unroll 8
    for (int m = 0; m < MPTS; m++) {
        float4 p = s_p2[m];
        float inner = fmaf(px, p.x, fmaf(py, p.y, pz * p.z));
        float d = fmaf(-2.0f, inner, sq1 + p.w);
        if (d < d2) {
            if (d < d1) {
                d2 = d1; i2 = i1;
                if (d < d0) { d1 = d0; i1 = i0; d0 = d; i0 = m; }
                else        { d1 = d;  i1 = m; }
            } else { d2 = d; i2 = m; }
        }
    }

    float r0 = 1.0f / fmaxf(sqrtf(fmaxf(d0, 1e-20f)), 1e-10f);
    float r1 = 1.0f / fmaxf(sqrtf(fmaxf(d1, 1e-20f)), 1e-10f);
    float r2 = 1.0f / fmaxf(sqrtf(fmaxf(d2, 1e-20f)), 1e-10f);
    float inv = 1.0f / (r0 + r1 + r2);

    const int base = (b * NPTS + n) * 3;
    g_idx[base + 0] = i0; g_idx[base + 1] = i1; g_idx[base + 2] = i2;
    g_wgt[base + 0] = r0 * inv; g_wgt[base + 1] = r1 * inv; g_wgt[base + 2] = r2 * inv;
}

// ===========================================================================
// fp16 mma.sync (m16n8k16) GEMM with ldmatrix + cp.async double buffer.
// 256-thr CTA, 8 warps (2x4), CTA tile 128x128, warp tile 64x32, BK=32.
//   MODE 0: Tt  = (W1h[:, :256] @ p2h)^T                  -> g_Tt [m][o] f32
//   MODE 1: y1h = h(relu(W1h[:,256:]@p1h + b1 + gather))  -> g_y1h
//   MODE 2: out = relu(W2h @ y1h + b2)                    -> d_out f32
// MODE 1: scattered gather interleaved into the chunk loop (ni group
// (cc+3)&3 gathered in chunk cc).
// ===========================================================================
#define BK    32
#define ASTR  40     // halves per As row (32 + 8 pad)
#define BSTR  136    // halves per Bs row (128 + 8 pad)

template <int MODE>
__global__ __launch_bounds__(256, 2)
void gemm_mma(const float* __restrict__ bias, float* __restrict__ Cext)
{
    constexpr int K    = (MODE == 1) ? 128 : 256;
    constexpr int NC   = K / BK;
    constexpr int LDA  = (MODE == 2) ? 256 : LDA_W1;
    constexpr int COFF = (MODE == 1) ? 256 : 0;
    constexpr int LDX  = (MODE == 0) ? MPTS : NPTS;
    constexpr int XBS  = (MODE == 0) ? CH2 * MPTS : (MODE == 1) ? CH1 * NPTS : OUT1 * NPTS;

    const __half* Ah = (MODE == 2) ? g_W2h : g_W1h;
    const __half* Xh = (MODE == 0) ? g_p2h : (MODE == 1) ? g_p1h : g_y1h;

    __shared__ __align__(16) __half As[2][128][ASTR];   // 20.0 KB
    __shared__ __align__(16) __half Bs[2][BK][BSTR];    // 17.4 KB
    __shared__ int   s_j[128 * 3];
    __shared__ float s_w[128 * 3];

    const int b     = blockIdx.z;
    const int nBase = blockIdx.x * 128;
    const int oBase = blockIdx.y * 128;
    const int tid   = threadIdx.x;
    const int wid   = tid >> 5;
    const int lane  = tid & 31;
    const int g     = lane >> 2;   // 0..7
    const int tc    = lane & 3;    // 0..3

    const int oW = (wid >> 2) * 64;   // 0 or 64
    const int nW = (wid & 3) * 32;    // 0,32,64,96

    const __half* Xb = Xh + (size_t)b * XBS;

    if (MODE == 1) {
        const int*   gi = g_idx + ((size_t)b * NPTS + nBase) * 3;
        const float* gw = g_wgt + ((size_t)b * NPTS + nBase) * 3;
        for (int i = tid; i < 384; i += 256) { s_j[i] = gi[i]; s_w[i] = gw[i]; }
    }

    // cp.async task mapping
    const int arow = tid & 127;
    const int akc0 = tid >> 7;
    const int bk0  = tid >> 4;
    const int bn8  = tid & 15;

    auto prefetch = [&](int c) {
        const int buf = c & 1;
        const int k0  = c * BK;
        const __half* ap = &Ah[(size_t)(oBase + arow) * LDA + COFF + k0];
        cp16(&As[buf][arow][8 * akc0],       ap + 8 * akc0);
        cp16(&As[buf][arow][8 * (akc0 + 2)], ap + 8 * (akc0 + 2));
        const __half* bp = &Xb[(size_t)k0 * LDX + nBase + 8 * bn8];
        cp16(&Bs[buf][bk0     ][8 * bn8], bp + (size_t)bk0 * LDX);
        cp16(&Bs[buf][bk0 + 16][8 * bn8], bp + (size_t)(bk0 + 16) * LDX);
        asm volatile("cp.async.commit_group;" ::: "memory");
    };

    // ldmatrix per-lane address offsets (bytes)
    const int lm = lane >> 3;
    const int lr = lane & 7;
    uint32_t aoff[4];
    #pragma unroll
    for (int mi = 0; mi < 4; mi++)
        aoff[mi] = ((oW + mi * 16 + lr + 8 * (lm & 1)) * ASTR + 8 * (lm >> 1)) * 2;
    uint32_t boff[2];
    #pragma unroll
    for (int pr = 0; pr < 2; pr++)
        boff[pr] = ((lr + 8 * (lm & 1)) * BSTR + nW + pr * 16 + 8 * (lm >> 1)) * 2;

    const uint32_t as_base = smem_u32(&As[0][0][0]);
    const uint32_t bs_base = smem_u32(&Bs[0][0][0]);
    constexpr uint32_t AS_BUF = 128 * ASTR * 2;
    constexpr uint32_t BS_BUF = BK * BSTR * 2;

    const float* Tb = g_Tt + (size_t)b * MPTS * OUT1;

    float c[4][4][4];
    #pragma unroll
    for (int mi = 0; mi < 4; mi++)
        #pragma unroll
        for (int ni = 0; ni < 4; ni++)
            #pragma unroll
            for (int q = 0; q < 4; q++) c[mi][ni][q] = 0.0f;

    prefetch(0);
    asm volatile("cp.async.wait_group 0;" ::: "memory");
    __syncthreads();

    for (int cc = 0; cc < NC; cc++) {
        const uint32_t asb = as_base + (cc & 1) * AS_BUF;
        const uint32_t bsb = bs_base + (cc & 1) * BS_BUF;
        if (cc + 1 < NC) prefetch(cc + 1);

        #pragma unroll
        for (int kk = 0; kk < BK; kk += 16) {
            uint32_t a[4][4];
            #pragma unroll
            for (int mi = 0; mi < 4; mi++)
                ldsm_x4(asb + aoff[mi] + kk * 2, a[mi][0], a[mi][1], a[mi][2], a[mi][3]);
            uint32_t bb[4][2];
            ldsm_x4t(bsb + boff[0] + kk * (BSTR * 2), bb[0][0], bb[0][1], bb[1][0], bb[1][1]);
            ldsm_x4t(bsb + boff[1] + kk * (BSTR * 2), bb[2][0], bb[2][1], bb[3][0], bb[3][1]);
            #pragma unroll
            for (int mi = 0; mi < 4; mi++)
                #pragma unroll
                for (int ni = 0; ni < 4; ni++) {
                    asm volatile(
                        "mma.sync.aligned.m16n8k16.row.col.f32.f16.f16.f32 "
                        "{%0,%1,%2,%3}, {%4,%5,%6,%7}, {%8,%9}, {%0,%1,%2,%3};"
                        : "+f"(c[mi][ni][0]), "+f"(c[mi][ni][1]),
                          "+f"(c[mi][ni][2]), "+f"(c[mi][ni][3])
                        : "r"(a[mi][0]), "r"(a[mi][1]), "r"(a[mi][2]), "r"(a[mi][3]),
                          "r"(bb[ni][0]), "r"(bb[ni][1]));
                }
        }

        if (MODE == 1) {
            const int gni = (cc + 3) & 3;
            #pragma unroll
            for (int t = 0; t < 2; t++) {
                const int ncta = nW + gni * 8 + tc * 2 + t;
                const int j0 = s_j[ncta * 3 + 0];
                const int j1 = s_j[ncta * 3 + 1];
                const int j2 = s_j[ncta * 3 + 2];
                const float w0 = s_w[ncta * 3 + 0];
                const float w1 = s_w[ncta * 3 + 1];
                const float w2 = s_w[ncta * 3 + 2];
                const float* r0 = Tb + (size_t)j0 * OUT1 + oBase + oW;
                const float* r1 = Tb + (size_t)j1 * OUT1 + oBase + oW;
                const float* r2 = Tb + (size_t)j2 * OUT1 + oBase + oW;
                #pragma unroll
                for (int mi = 0; mi < 4; mi++) {
                    #pragma unroll
                    for (int h = 0; h < 2; h++) {
                        const int ol = mi * 16 + g + h * 8;
                        c[mi][gni][h * 2 + t] +=
                            w0 * __ldg(&r0[ol]) + w1 * __ldg(&r1[ol]) + w2 * __ldg(&r2[ol]);
                    }
                }
            }
        }

        asm volatile("cp.async.wait_group 0;" ::: "memory");
        __syncthreads();
    }

    // ---- epilogue ----
    if (MODE == 0) {
        float* Cb = g_Tt + (size_t)b * MPTS * OUT1;
        #pragma unroll
        for (int ni = 0; ni < 4; ni++) {
            #pragma unroll
            for (int t = 0; t < 2; t++) {
                int m = nBase + nW + ni * 8 + tc * 2 + t;
                float* mrow = Cb + (size_t)m * OUT1;
                #pragma unroll
                for (int mi = 0; mi < 4; mi++) {
                    #pragma unroll
                    for (int h = 0; h < 2; h++) {
                        int o = oBase + oW + mi * 16 + g + h * 8;
                        mrow[o] = c[mi][ni][h * 2 + t];
                    }
                }
            }
        }
        return;
    }

    if (MODE == 1) {
        __half* Cb = g_y1h + (size_t)b * OUT1 * NPTS;
        #pragma unroll
        for (int mi = 0; mi < 4; mi++) {
            #pragma unroll
            for (int h = 0; h < 2; h++) {
                int o = oBase + oW + mi * 16 + g + h * 8;
                float bv = bias[o];
                __half* orow = Cb + (size_t)o * NPTS;
                #pragma unroll
                for (int ni = 0; ni < 4; ni++) {
                    int n = nBase + nW + ni * 8 + tc * 2;
                    float v0 = fmaxf(c[mi][ni][h * 2 + 0] + bv, 0.0f);
                    float v1 = fmaxf(c[mi][ni][h * 2 + 1] + bv, 0.0f);
                    *reinterpret_cast<__half2*>(&orow[n]) = __floats2half2_rn(v0, v1);
                }
            }
        }
        return;
    }

    // MODE 2: final output fp32
    float* Cb = Cext + (size_t)b * OUT2 * NPTS;
    #pragma unroll
    for (int mi = 0; mi < 4; mi++) {
        #pragma unroll
        for (int h = 0; h < 2; h++) {
            int o = oBase + oW + mi * 16 + g + h * 8;
            float bv = bias[o];
            float* orow = Cb + (size_t)o * NPTS;
            #pragma unroll
            for (int ni = 0; ni < 4; ni++) {
                int n = nBase + nW + ni * 8 + tc * 2;
                float v0 = fmaxf(c[mi][ni][h * 2 + 0] + bv, 0.0f);
                float v1 = fmaxf(c[mi][ni][h * 2 + 1] + bv, 0.0f);
                *reinterpret_cast<float2*>(&orow[n]) = make_float2(v0, v1);
            }
        }
    }
}

// ===========================================================================
extern "C" void kernel_launch(void* const* d_in, const int* in_sizes, int n_in,
                              void* d_out, int out_size)
{
    const float* xyz1    = (const float*)d_in[0];
    const float* xyz2    = (const float*)d_in[1];
    const float* points1 = (const float*)d_in[2];
    const float* points2 = (const float*)d_in[3];
    const float* W1      = (const float*)d_in[4];
    const float* b1      = (const float*)d_in[5];
    const float* W2      = (const float*)d_in[6];
    const float* b2      = (const float*)d_in[7];
    float*       out     = (float*)d_out;

    // three_nn + fp16 conversion, overlapped in one grid
    prep_kernel<<<512, 256>>>(xyz1, xyz2, W1, W2, points1, points2);

    // Tt = (W1[:, :256] @ points2)^T   (fp32)
    gemm_mma<0><<<dim3(MPTS / 128, OUT1 / 128, NB), 256>>>(nullptr, nullptr);

    // y1h = half(relu(W1[:, 256:] @ points1 + b1 + gathered Tt))
    gemm_mma<1><<<dim3(NPTS / 128, OUT1 / 128, NB), 256>>>(b1, nullptr);

    // out = relu(W2 @ y1h + b2)
    gemm_mma<2><<<dim3(NPTS / 128, OUT2 / 128, NB), 256>>>(b2, out);
}